// round 10
// baseline (speedup 1.0000x reference)
#include <cuda_runtime.h>
#include <cstdint>

// Problem constants (fixed by the dataset)
#define NN      100000      // nodes
#define DIN     256         // input feature dim
#define DOUT    32          // output feature dim
#define GTHREADS 256        // 8 warps
#define RPW     16          // rows per warp (m16)
#define RPB     (RPW * 8)   // 128 rows per block
#define NKS     (DIN / 8)   // 32 k-steps of k8
#define CHUNK_COLS 32       // k-columns per pipeline chunk
#define KSPC    4           // k-steps per chunk
#define NCHUNK  (DIN / CHUNK_COLS)   // 8
#define XS_STRIDE 36        // floats per staged row (bank-spread, 16B aligned)
#define XBUF_FLOATS (RPB * XS_STRIDE)
#define BFRAG_N (NKS * 4 * 32)                  // 4096 uint2
#define BFRAG_BYTES (BFRAG_N * 8)               // 32 KB
#define SMEM_BYTES  (BFRAG_BYTES + 2 * XBUF_FLOATS * 4)

// ---- Device-global scratch (per rules) ----
__device__ float g_presup[(size_t)NN * DOUT];   // 12.8 MB
__device__ uint2 g_bfrag[BFRAG_N];              // 32 KB

// ===========================================================================
// GEMM (tf32 mma.sync): Round-9 version (measured 32.7 us), unchanged.
// ===========================================================================
__device__ __forceinline__ uint32_t f2tf32(float f) {
    uint32_t u;
    asm("cvt.rna.tf32.f32 %0, %1;" : "=r"(u) : "f"(f));
    return u;
}

__device__ __forceinline__ void mma_tf32(float4& d,
                                         uint32_t a0, uint32_t a1, uint32_t a2, uint32_t a3,
                                         uint32_t b0, uint32_t b1) {
    asm volatile("mma.sync.aligned.m16n8k8.row.col.f32.tf32.tf32.f32 "
                 "{%0,%1,%2,%3}, {%4,%5,%6,%7}, {%8,%9}, {%0,%1,%2,%3};"
                 : "+f"(d.x), "+f"(d.y), "+f"(d.z), "+f"(d.w)
                 : "r"(a0), "r"(a1), "r"(a2), "r"(a3), "r"(b0), "r"(b1));
}

__device__ __forceinline__ uint32_t smem_u32(const void* p) {
    uint32_t a;
    asm("{ .reg .u64 t; cvta.to.shared.u64 t, %1; cvt.u32.u64 %0, t; }"
        : "=r"(a) : "l"(p));
    return a;
}

__device__ __forceinline__ void cp_async16(uint32_t dst, const void* src, int nbytes) {
    asm volatile("cp.async.ca.shared.global [%0], [%1], 16, %2;"
                 :: "r"(dst), "l"(src), "r"(nbytes) : "memory");
}

__device__ __forceinline__ void issue_chunk(uint32_t xs_addr, const float* __restrict__ x,
                                            int row0, int kc, int tid) {
#pragma unroll
    for (int j = 0; j < 4; j++) {
        int i    = tid + j * GTHREADS;
        int r    = i >> 3;
        int seg  = i & 7;
        int grow = row0 + r;
        int gsrc = (grow < NN) ? grow : (NN - 1);
        const float* src = x + (size_t)gsrc * DIN + kc + seg * 4;
        uint32_t dst = xs_addr + (uint32_t)(r * (XS_STRIDE * 4) + seg * 16);
        cp_async16(dst, src, (grow < NN) ? 16 : 0);
    }
    asm volatile("cp.async.commit_group;" ::: "memory");
}

// Precompute B fragments once (grid 16 x 256)
__global__ void bfrag_kernel(const float* __restrict__ w) {
    int i = blockIdx.x * 256 + threadIdx.x;
    if (i >= BFRAG_N) return;
    int ks  = i >> 7;
    int rem = i & 127;
    int nb  = rem >> 5;
    int ln  = rem & 31;
    int t = ln & 3, g = ln >> 2;
    float w0 = w[(ks * 8 + t)     * DOUT + nb * 8 + g];
    float w1 = w[(ks * 8 + t + 4) * DOUT + nb * 8 + g];
    g_bfrag[i] = make_uint2(f2tf32(w0), f2tf32(w1));
}

__global__ __launch_bounds__(GTHREADS, 3) void gemm_kernel(const float* __restrict__ x) {
    extern __shared__ char smem[];
    uint2* Bfrag = (uint2*)smem;                         // 32 KB
    float* Xbuf  = (float*)(smem + BFRAG_BYTES);
    const uint32_t xb_addr0 = smem_u32(Xbuf);
    const uint32_t xb_addr1 = xb_addr0 + XBUF_FLOATS * 4;

    const int tid  = threadIdx.x;
    const int row0 = blockIdx.x * RPB;

    issue_chunk(xb_addr0, x, row0, 0,          tid);
    issue_chunk(xb_addr1, x, row0, CHUNK_COLS, tid);

    // Linear copy of precomputed B fragments (coalesced LDG.128)
    {
        const uint4* src = (const uint4*)g_bfrag;
        uint4* dst = (uint4*)Bfrag;
#pragma unroll
        for (int i = 0; i < BFRAG_N / 2 / GTHREADS; i++)
            dst[tid + i * GTHREADS] = src[tid + i * GTHREADS];
    }

    const int wid  = tid >> 5;
    const int lane = tid & 31;
    const int t    = lane & 3;
    const int g    = lane >> 2;
    const int rl   = wid * RPW;

    float4 acc[4];
#pragma unroll
    for (int nb = 0; nb < 4; nb++) acc[nb] = make_float4(0.f, 0.f, 0.f, 0.f);

    const int offA = (rl + g) * XS_STRIDE + t;
    const int offB = (rl + g + 8) * XS_STRIDE + t;

#pragma unroll
    for (int c = 0; c < NCHUNK; c++) {
        if (c < NCHUNK - 1)
            asm volatile("cp.async.wait_group 1;" ::: "memory");
        else
            asm volatile("cp.async.wait_group 0;" ::: "memory");
        __syncthreads();

        const float* Xs = Xbuf + (c & 1) * XBUF_FLOATS;
#pragma unroll
        for (int ksl = 0; ksl < KSPC; ksl++) {
            const int k0 = ksl * 8;
            uint32_t a0 = f2tf32(Xs[offA + k0]);
            uint32_t a1 = f2tf32(Xs[offB + k0]);
            uint32_t a2 = f2tf32(Xs[offA + k0 + 4]);
            uint32_t a3 = f2tf32(Xs[offB + k0 + 4]);

            const uint2* bp = Bfrag + (c * KSPC + ksl) * 4 * 32 + lane;
            uint2 b0 = bp[0 * 32];
            uint2 b1 = bp[1 * 32];
            uint2 b2 = bp[2 * 32];
            uint2 b3 = bp[3 * 32];
            mma_tf32(acc[0], a0, a1, a2, a3, b0.x, b0.y);
            mma_tf32(acc[1], a0, a1, a2, a3, b1.x, b1.y);
            mma_tf32(acc[2], a0, a1, a2, a3, b2.x, b2.y);
            mma_tf32(acc[3], a0, a1, a2, a3, b3.x, b3.y);
        }

        if (c + 2 < NCHUNK) {
            __syncthreads();
            issue_chunk((c & 1) ? xb_addr1 : xb_addr0, x, row0,
                        (c + 2) * CHUNK_COLS, tid);
        }
    }

    const int r0 = row0 + rl + g;
    const int r1 = row0 + rl + g + 8;
#pragma unroll
    for (int nb = 0; nb < 4; nb++) {
        if (r0 < NN)
            *(float2*)(g_presup + (size_t)r0 * DOUT + nb * 8 + 2 * t) =
                make_float2(acc[nb].x, acc[nb].y);
        if (r1 < NN)
            *(float2*)(g_presup + (size_t)r1 * DOUT + nb * 8 + 2 * t) =
                make_float2(acc[nb].z, acc[nb].w);
    }
}

// ===========================================================================
// Scatter SpMM  out[row[e]] += val[e] * pre_sup[col[e]]
// ONE thread per edge: 3 coalesced index loads + 8 LDG.128 (same L2 line,
// MLP=8) + 8 red.global.add.v4.f32. 19 instrs/edge vs 40 for 8 t/e.
// ===========================================================================
__global__ __launch_bounds__(256) void scatter_kernel(const int*   __restrict__ arow,
                                                      const int*   __restrict__ acol,
                                                      const float* __restrict__ aval,
                                                      float*       __restrict__ out,
                                                      int n_edges) {
    int e = blockIdx.x * 256 + threadIdx.x;
    if (e >= n_edges) return;

    int   r = __ldg(arow + e);
    int   c = __ldg(acol + e);
    float v = __ldg(aval + e);

    const float4* src = (const float4*)(g_presup + (size_t)c * DOUT);
    float*        dst = out + (size_t)r * DOUT;

    float4 p[8];
#pragma unroll
    for (int j = 0; j < 8; j++) p[j] = __ldg(src + j);

#pragma unroll
    for (int j = 0; j < 8; j++) {
        float m0 = v * p[j].x, m1 = v * p[j].y, m2 = v * p[j].z, m3 = v * p[j].w;
        asm volatile("red.global.add.v4.f32 [%0], {%1, %2, %3, %4};"
                     :: "l"(dst + j * 4), "f"(m0), "f"(m1), "f"(m2), "f"(m3)
                     : "memory");
    }
}

// ===========================================================================
// ReLU in place
// ===========================================================================
__global__ __launch_bounds__(256) void relu_kernel(float* __restrict__ out, int n4) {
    int i = blockIdx.x * 256 + threadIdx.x;
    if (i < n4) {
        float4 v = ((float4*)out)[i];
        v.x = fmaxf(v.x, 0.f);
        v.y = fmaxf(v.y, 0.f);
        v.z = fmaxf(v.z, 0.f);
        v.w = fmaxf(v.w, 0.f);
        ((float4*)out)[i] = v;
    }
}

// ===========================================================================
// kernel_launch: bfrag -> memset(out) -> gemm -> scatter -> relu
// ===========================================================================
extern "C" void kernel_launch(void* const* d_in, const int* in_sizes, int n_in,
                              void* d_out, int out_size) {
    const float* x    = (const float*)d_in[0];
    const int*   arow = (const int*)  d_in[1];
    const int*   acol = (const int*)  d_in[2];
    const float* aval = (const float*)d_in[3];
    const float* w    = (const float*)d_in[4];
    float*       out  = (float*)d_out;

    const int n_edges = in_sizes[1];

    cudaFuncSetAttribute(gemm_kernel, cudaFuncAttributeMaxDynamicSharedMemorySize,
                         SMEM_BYTES);

    bfrag_kernel<<<(BFRAG_N + 255) / 256, 256>>>(w);
    cudaMemsetAsync(out, 0, (size_t)out_size * sizeof(float), 0);

    gemm_kernel<<<(NN + RPB - 1) / RPB, GTHREADS, SMEM_BYTES>>>(x);

    scatter_kernel<<<(n_edges + 255) / 256, 256>>>(arow, acol, aval, out, n_edges);

    int n4 = out_size / 4;
    relu_kernel<<<(n4 + 255) / 256, 256>>>(out, n4);
}

// round 11
// speedup vs baseline: 1.0739x; 1.0739x over previous
#include <cuda_runtime.h>
#include <cstdint>

// Problem constants (fixed by the dataset)
#define NN      100000      // nodes
#define DIN     256         // input feature dim
#define DOUT    32          // output feature dim
#define GTHREADS 256        // 8 warps
#define RPW     16          // rows per warp (m16)
#define RPB     (RPW * 8)   // 128 rows per block
#define NKS     (DIN / 8)   // 32 k-steps of k8
#define CHUNK_COLS 32       // k-columns per pipeline chunk
#define KSPC    4           // k-steps per chunk
#define NCHUNK  (DIN / CHUNK_COLS)   // 8
#define XS_STRIDE 36        // floats per staged row (bank-spread, 16B aligned)
#define XBUF_FLOATS (RPB * XS_STRIDE)
#define BFRAG_N (NKS * 4 * 32)                  // 4096 uint2
#define SMEM_BYTES  (2 * XBUF_FLOATS * 4)       // 36 KB (2 X buffers only)

// ---- Device-global scratch (per rules) ----
__device__ float g_presup[(size_t)NN * DOUT];   // 12.8 MB
__device__ uint2 g_bfrag[BFRAG_N];              // 32 KB (L1-resident, read-only)

// ===========================================================================
// GEMM (tf32 mma.sync). B fragments precomputed once to global and read
// directly in the mainloop (L1-hit LDG.64, no smem copy) -> smem = 36 KB
// -> 6 blocks/SM resident (occ ~75%) for latency hiding.
// ===========================================================================
__device__ __forceinline__ uint32_t f2tf32(float f) {
    uint32_t u;
    asm("cvt.rna.tf32.f32 %0, %1;" : "=r"(u) : "f"(f));
    return u;
}

__device__ __forceinline__ void mma_tf32(float4& d,
                                         uint32_t a0, uint32_t a1, uint32_t a2, uint32_t a3,
                                         uint32_t b0, uint32_t b1) {
    asm volatile("mma.sync.aligned.m16n8k8.row.col.f32.tf32.tf32.f32 "
                 "{%0,%1,%2,%3}, {%4,%5,%6,%7}, {%8,%9}, {%0,%1,%2,%3};"
                 : "+f"(d.x), "+f"(d.y), "+f"(d.z), "+f"(d.w)
                 : "r"(a0), "r"(a1), "r"(a2), "r"(a3), "r"(b0), "r"(b1));
}

__device__ __forceinline__ uint32_t smem_u32(const void* p) {
    uint32_t a;
    asm("{ .reg .u64 t; cvta.to.shared.u64 t, %1; cvt.u32.u64 %0, t; }"
        : "=r"(a) : "l"(p));
    return a;
}

__device__ __forceinline__ void cp_async16(uint32_t dst, const void* src, int nbytes) {
    asm volatile("cp.async.ca.shared.global [%0], [%1], 16, %2;"
                 :: "r"(dst), "l"(src), "r"(nbytes) : "memory");
}

__device__ __forceinline__ void issue_chunk(uint32_t xs_addr, const float* __restrict__ x,
                                            int row0, int kc, int tid) {
#pragma unroll
    for (int j = 0; j < 4; j++) {
        int i    = tid + j * GTHREADS;
        int r    = i >> 3;
        int seg  = i & 7;
        int grow = row0 + r;
        int gsrc = (grow < NN) ? grow : (NN - 1);
        const float* src = x + (size_t)gsrc * DIN + kc + seg * 4;
        uint32_t dst = xs_addr + (uint32_t)(r * (XS_STRIDE * 4) + seg * 16);
        cp_async16(dst, src, (grow < NN) ? 16 : 0);
    }
    asm volatile("cp.async.commit_group;" ::: "memory");
}

// Precompute B fragments once (grid 16 x 256)
__global__ void bfrag_kernel(const float* __restrict__ w) {
    int i = blockIdx.x * 256 + threadIdx.x;
    if (i >= BFRAG_N) return;
    int ks  = i >> 7;
    int rem = i & 127;
    int nb  = rem >> 5;
    int ln  = rem & 31;
    int t = ln & 3, g = ln >> 2;
    float w0 = w[(ks * 8 + t)     * DOUT + nb * 8 + g];
    float w1 = w[(ks * 8 + t + 4) * DOUT + nb * 8 + g];
    g_bfrag[i] = make_uint2(f2tf32(w0), f2tf32(w1));
}

__global__ __launch_bounds__(GTHREADS, 6) void gemm_kernel(const float* __restrict__ x) {
    extern __shared__ char smem[];
    float* Xbuf  = (float*)smem;                         // 2 x 18 KB
    const uint32_t xb_addr0 = smem_u32(Xbuf);
    const uint32_t xb_addr1 = xb_addr0 + XBUF_FLOATS * 4;

    const int tid  = threadIdx.x;
    const int row0 = blockIdx.x * RPB;

    issue_chunk(xb_addr0, x, row0, 0,          tid);
    issue_chunk(xb_addr1, x, row0, CHUNK_COLS, tid);

    const int wid  = tid >> 5;
    const int lane = tid & 31;
    const int t    = lane & 3;
    const int g    = lane >> 2;
    const int rl   = wid * RPW;

    float4 acc[4];
#pragma unroll
    for (int nb = 0; nb < 4; nb++) acc[nb] = make_float4(0.f, 0.f, 0.f, 0.f);

    const int offA = (rl + g) * XS_STRIDE + t;
    const int offB = (rl + g + 8) * XS_STRIDE + t;

#pragma unroll
    for (int c = 0; c < NCHUNK; c++) {
        if (c < NCHUNK - 1)
            asm volatile("cp.async.wait_group 1;" ::: "memory");
        else
            asm volatile("cp.async.wait_group 0;" ::: "memory");
        __syncthreads();

        const float* Xs = Xbuf + (c & 1) * XBUF_FLOATS;
#pragma unroll
        for (int ksl = 0; ksl < KSPC; ksl++) {
            const int k0 = ksl * 8;
            uint32_t a0 = f2tf32(Xs[offA + k0]);
            uint32_t a1 = f2tf32(Xs[offB + k0]);
            uint32_t a2 = f2tf32(Xs[offA + k0 + 4]);
            uint32_t a3 = f2tf32(Xs[offB + k0 + 4]);

            // B fragments straight from global (L1-resident, read-only)
            const uint2* bp = g_bfrag + (c * KSPC + ksl) * 4 * 32 + lane;
            uint2 b0 = __ldg(bp + 0 * 32);
            uint2 b1 = __ldg(bp + 1 * 32);
            uint2 b2 = __ldg(bp + 2 * 32);
            uint2 b3 = __ldg(bp + 3 * 32);
            mma_tf32(acc[0], a0, a1, a2, a3, b0.x, b0.y);
            mma_tf32(acc[1], a0, a1, a2, a3, b1.x, b1.y);
            mma_tf32(acc[2], a0, a1, a2, a3, b2.x, b2.y);
            mma_tf32(acc[3], a0, a1, a2, a3, b3.x, b3.y);
        }

        if (c + 2 < NCHUNK) {
            __syncthreads();
            issue_chunk((c & 1) ? xb_addr1 : xb_addr0, x, row0,
                        (c + 2) * CHUNK_COLS, tid);
        }
    }

    const int r0 = row0 + rl + g;
    const int r1 = row0 + rl + g + 8;
#pragma unroll
    for (int nb = 0; nb < 4; nb++) {
        if (r0 < NN)
            *(float2*)(g_presup + (size_t)r0 * DOUT + nb * 8 + 2 * t) =
                make_float2(acc[nb].x, acc[nb].y);
        if (r1 < NN)
            *(float2*)(g_presup + (size_t)r1 * DOUT + nb * 8 + 2 * t) =
                make_float2(acc[nb].z, acc[nb].w);
    }
}

// ===========================================================================
// Scatter SpMM  out[row[e]] += val[e] * pre_sup[col[e]]
// 8 threads per edge (lane-level coalescing: one warp instruction covers
// 4 rows x 128B = 4 wavefronts). One float4 gather + one red.v4 per thread.
// ===========================================================================
__global__ __launch_bounds__(256) void scatter_kernel(const int*   __restrict__ arow,
                                                      const int*   __restrict__ acol,
                                                      const float* __restrict__ aval,
                                                      float*       __restrict__ out,
                                                      int n_edges) {
    long long gdx = (long long)blockIdx.x * blockDim.x + threadIdx.x;
    int e    = (int)(gdx >> 3);
    int part = (int)(gdx & 7);
    if (e >= n_edges) return;

    int   r = arow[e];
    int   c = acol[e];
    float v = aval[e];

    float4 p = *(const float4*)(g_presup + (size_t)c * DOUT + part * 4);
    float m0 = v * p.x, m1 = v * p.y, m2 = v * p.z, m3 = v * p.w;

    float* dst = out + (size_t)r * DOUT + part * 4;
    asm volatile("red.global.add.v4.f32 [%0], {%1, %2, %3, %4};"
                 :: "l"(dst), "f"(m0), "f"(m1), "f"(m2), "f"(m3)
                 : "memory");
}

// ===========================================================================
// ReLU in place
// ===========================================================================
__global__ __launch_bounds__(256) void relu_kernel(float* __restrict__ out, int n4) {
    int i = blockIdx.x * 256 + threadIdx.x;
    if (i < n4) {
        float4 v = ((float4*)out)[i];
        v.x = fmaxf(v.x, 0.f);
        v.y = fmaxf(v.y, 0.f);
        v.z = fmaxf(v.z, 0.f);
        v.w = fmaxf(v.w, 0.f);
        ((float4*)out)[i] = v;
    }
}

// ===========================================================================
// kernel_launch: bfrag -> memset(out) -> gemm -> scatter -> relu
// ===========================================================================
extern "C" void kernel_launch(void* const* d_in, const int* in_sizes, int n_in,
                              void* d_out, int out_size) {
    const float* x    = (const float*)d_in[0];
    const int*   arow = (const int*)  d_in[1];
    const int*   acol = (const int*)  d_in[2];
    const float* aval = (const float*)d_in[3];
    const float* w    = (const float*)d_in[4];
    float*       out  = (float*)d_out;

    const int n_edges = in_sizes[1];

    cudaFuncSetAttribute(gemm_kernel, cudaFuncAttributeMaxDynamicSharedMemorySize,
                         SMEM_BYTES);

    bfrag_kernel<<<(BFRAG_N + 255) / 256, 256>>>(w);
    cudaMemsetAsync(out, 0, (size_t)out_size * sizeof(float), 0);

    gemm_kernel<<<(NN + RPB - 1) / RPB, GTHREADS, SMEM_BYTES>>>(x);

    long long sthreads = (long long)n_edges * 8;
    int sblocks = (int)((sthreads + 255) / 256);
    scatter_kernel<<<sblocks, 256>>>(arow, acol, aval, out, n_edges);

    int n4 = out_size / 4;
    relu_kernel<<<(n4 + 255) / 256, 256>>>(out, n4);
}

// round 12
// speedup vs baseline: 1.5990x; 1.4889x over previous
#include <cuda_runtime.h>
#include <cstdint>

// Problem constants (fixed by the dataset)
#define NN      100000      // nodes
#define DIN     256         // input feature dim
#define DOUT    32          // output feature dim
#define GTHREADS 256        // 8 warps
#define RPW     16          // rows per warp (m16)
#define RPB     (RPW * 8)   // 128 rows per block
#define NKS     (DIN / 8)   // 32 k-steps of k8
#define CHUNK_COLS 32       // k-columns per pipeline chunk
#define KSPC    4           // k-steps per chunk
#define NCHUNK  (DIN / CHUNK_COLS)   // 8
#define XS_STRIDE 36        // floats per staged row (bank-spread, 16B aligned)
#define XBUF_FLOATS (RPB * XS_STRIDE)
#define BFRAG_N (NKS * 4 * 32)                  // 4096 uint2
#define BFRAG_BYTES (BFRAG_N * 8)               // 32 KB
#define SMEM_BYTES  (BFRAG_BYTES + 2 * XBUF_FLOATS * 4)   // 68 KB

// ---- Device-global scratch (per rules) ----
__device__ float g_presup[(size_t)NN * DOUT];   // 12.8 MB
__device__ uint2 g_bfrag[BFRAG_N];              // 32 KB

// ===========================================================================
// GEMM (tf32 mma.sync): exact Round-9 version (measured 32.7 us).
// B fragments precomputed once to global, linearly copied into smem per block.
// X tile cp.async double-buffered, stride-36 bank-spread fragment reads.
// ===========================================================================
__device__ __forceinline__ uint32_t f2tf32(float f) {
    uint32_t u;
    asm("cvt.rna.tf32.f32 %0, %1;" : "=r"(u) : "f"(f));
    return u;
}

__device__ __forceinline__ void mma_tf32(float4& d,
                                         uint32_t a0, uint32_t a1, uint32_t a2, uint32_t a3,
                                         uint32_t b0, uint32_t b1) {
    asm volatile("mma.sync.aligned.m16n8k8.row.col.f32.tf32.tf32.f32 "
                 "{%0,%1,%2,%3}, {%4,%5,%6,%7}, {%8,%9}, {%0,%1,%2,%3};"
                 : "+f"(d.x), "+f"(d.y), "+f"(d.z), "+f"(d.w)
                 : "r"(a0), "r"(a1), "r"(a2), "r"(a3), "r"(b0), "r"(b1));
}

__device__ __forceinline__ uint32_t smem_u32(const void* p) {
    uint32_t a;
    asm("{ .reg .u64 t; cvta.to.shared.u64 t, %1; cvt.u32.u64 %0, t; }"
        : "=r"(a) : "l"(p));
    return a;
}

__device__ __forceinline__ void cp_async16(uint32_t dst, const void* src, int nbytes) {
    asm volatile("cp.async.ca.shared.global [%0], [%1], 16, %2;"
                 :: "r"(dst), "l"(src), "r"(nbytes) : "memory");
}

__device__ __forceinline__ void issue_chunk(uint32_t xs_addr, const float* __restrict__ x,
                                            int row0, int kc, int tid) {
#pragma unroll
    for (int j = 0; j < 4; j++) {
        int i    = tid + j * GTHREADS;
        int r    = i >> 3;
        int seg  = i & 7;
        int grow = row0 + r;
        int gsrc = (grow < NN) ? grow : (NN - 1);
        const float* src = x + (size_t)gsrc * DIN + kc + seg * 4;
        uint32_t dst = xs_addr + (uint32_t)(r * (XS_STRIDE * 4) + seg * 16);
        cp_async16(dst, src, (grow < NN) ? 16 : 0);
    }
    asm volatile("cp.async.commit_group;" ::: "memory");
}

// Precompute B fragments once (grid 16 x 256)
__global__ void bfrag_kernel(const float* __restrict__ w) {
    int i = blockIdx.x * 256 + threadIdx.x;
    if (i >= BFRAG_N) return;
    int ks  = i >> 7;
    int rem = i & 127;
    int nb  = rem >> 5;
    int ln  = rem & 31;
    int t = ln & 3, g = ln >> 2;
    float w0 = w[(ks * 8 + t)     * DOUT + nb * 8 + g];
    float w1 = w[(ks * 8 + t + 4) * DOUT + nb * 8 + g];
    g_bfrag[i] = make_uint2(f2tf32(w0), f2tf32(w1));
}

__global__ __launch_bounds__(GTHREADS, 3) void gemm_kernel(const float* __restrict__ x) {
    extern __shared__ char smem[];
    uint2* Bfrag = (uint2*)smem;                         // 32 KB
    float* Xbuf  = (float*)(smem + BFRAG_BYTES);         // 2 x 18 KB
    const uint32_t xb_addr0 = smem_u32(Xbuf);
    const uint32_t xb_addr1 = xb_addr0 + XBUF_FLOATS * 4;

    const int tid  = threadIdx.x;
    const int row0 = blockIdx.x * RPB;

    issue_chunk(xb_addr0, x, row0, 0,          tid);
    issue_chunk(xb_addr1, x, row0, CHUNK_COLS, tid);

    // Linear copy of precomputed B fragments (coalesced LDG.128)
    {
        const uint4* src = (const uint4*)g_bfrag;
        uint4* dst = (uint4*)Bfrag;
#pragma unroll
        for (int i = 0; i < BFRAG_N / 2 / GTHREADS; i++)
            dst[tid + i * GTHREADS] = src[tid + i * GTHREADS];
    }

    const int wid  = tid >> 5;
    const int lane = tid & 31;
    const int t    = lane & 3;
    const int g    = lane >> 2;
    const int rl   = wid * RPW;

    float4 acc[4];
#pragma unroll
    for (int nb = 0; nb < 4; nb++) acc[nb] = make_float4(0.f, 0.f, 0.f, 0.f);

    const int offA = (rl + g) * XS_STRIDE + t;
    const int offB = (rl + g + 8) * XS_STRIDE + t;

#pragma unroll
    for (int c = 0; c < NCHUNK; c++) {
        if (c < NCHUNK - 1)
            asm volatile("cp.async.wait_group 1;" ::: "memory");
        else
            asm volatile("cp.async.wait_group 0;" ::: "memory");
        __syncthreads();

        const float* Xs = Xbuf + (c & 1) * XBUF_FLOATS;
#pragma unroll
        for (int ksl = 0; ksl < KSPC; ksl++) {
            const int k0 = ksl * 8;
            uint32_t a0 = f2tf32(Xs[offA + k0]);
            uint32_t a1 = f2tf32(Xs[offB + k0]);
            uint32_t a2 = f2tf32(Xs[offA + k0 + 4]);
            uint32_t a3 = f2tf32(Xs[offB + k0 + 4]);

            const uint2* bp = Bfrag + (c * KSPC + ksl) * 4 * 32 + lane;
            uint2 b0 = bp[0 * 32];
            uint2 b1 = bp[1 * 32];
            uint2 b2 = bp[2 * 32];
            uint2 b3 = bp[3 * 32];
            mma_tf32(acc[0], a0, a1, a2, a3, b0.x, b0.y);
            mma_tf32(acc[1], a0, a1, a2, a3, b1.x, b1.y);
            mma_tf32(acc[2], a0, a1, a2, a3, b2.x, b2.y);
            mma_tf32(acc[3], a0, a1, a2, a3, b3.x, b3.y);
        }

        if (c + 2 < NCHUNK) {
            __syncthreads();
            issue_chunk((c & 1) ? xb_addr1 : xb_addr0, x, row0,
                        (c + 2) * CHUNK_COLS, tid);
        }
    }

    const int r0 = row0 + rl + g;
    const int r1 = row0 + rl + g + 8;
#pragma unroll
    for (int nb = 0; nb < 4; nb++) {
        if (r0 < NN)
            *(float2*)(g_presup + (size_t)r0 * DOUT + nb * 8 + 2 * t) =
                make_float2(acc[nb].x, acc[nb].y);
        if (r1 < NN)
            *(float2*)(g_presup + (size_t)r1 * DOUT + nb * 8 + 2 * t) =
                make_float2(acc[nb].z, acc[nb].w);
    }
}

// ===========================================================================
// Scatter SpMM  out[row[e]] += val[e] * pre_sup[col[e]]
// Exact Round-8 version: 8 threads per edge (lane-level coalescing),
// one float4 gather + one red.global.add.v4.f32 per thread.
// ===========================================================================
__global__ __launch_bounds__(256) void scatter_kernel(const int*   __restrict__ arow,
                                                      const int*   __restrict__ acol,
                                                      const float* __restrict__ aval,
                                                      float*       __restrict__ out,
                                                      int n_edges) {
    long long gdx = (long long)blockIdx.x * blockDim.x + threadIdx.x;
    int e    = (int)(gdx >> 3);
    int part = (int)(gdx & 7);
    if (e >= n_edges) return;

    int   r = arow[e];
    int   c = acol[e];
    float v = aval[e];

    float4 p = *(const float4*)(g_presup + (size_t)c * DOUT + part * 4);
    float m0 = v * p.x, m1 = v * p.y, m2 = v * p.z, m3 = v * p.w;

    float* dst = out + (size_t)r * DOUT + part * 4;
    asm volatile("red.global.add.v4.f32 [%0], {%1, %2, %3, %4};"
                 :: "l"(dst), "f"(m0), "f"(m1), "f"(m2), "f"(m3)
                 : "memory");
}

// ===========================================================================
// ReLU in place
// ===========================================================================
__global__ __launch_bounds__(256) void relu_kernel(float* __restrict__ out, int n4) {
    int i = blockIdx.x * 256 + threadIdx.x;
    if (i < n4) {
        float4 v = ((float4*)out)[i];
        v.x = fmaxf(v.x, 0.f);
        v.y = fmaxf(v.y, 0.f);
        v.z = fmaxf(v.z, 0.f);
        v.w = fmaxf(v.w, 0.f);
        ((float4*)out)[i] = v;
    }
}

// ===========================================================================
// kernel_launch: bfrag -> memset(out) -> gemm -> scatter -> relu
// ===========================================================================
extern "C" void kernel_launch(void* const* d_in, const int* in_sizes, int n_in,
                              void* d_out, int out_size) {
    const float* x    = (const float*)d_in[0];
    const int*   arow = (const int*)  d_in[1];
    const int*   acol = (const int*)  d_in[2];
    const float* aval = (const float*)d_in[3];
    const float* w    = (const float*)d_in[4];
    float*       out  = (float*)d_out;

    const int n_edges = in_sizes[1];

    cudaFuncSetAttribute(gemm_kernel, cudaFuncAttributeMaxDynamicSharedMemorySize,
                         SMEM_BYTES);

    bfrag_kernel<<<(BFRAG_N + 255) / 256, 256>>>(w);
    cudaMemsetAsync(out, 0, (size_t)out_size * sizeof(float), 0);

    gemm_kernel<<<(NN + RPB - 1) / RPB, GTHREADS, SMEM_BYTES>>>(x);

    long long sthreads = (long long)n_edges * 8;
    int sblocks = (int)((sthreads + 255) / 256);
    scatter_kernel<<<sblocks, 256>>>(arow, acol, aval, out, n_edges);

    int n4 = out_size / 4;
    relu_kernel<<<(n4 + 255) / 256, 256>>>(out, n4);
}

// round 13
// speedup vs baseline: 1.6749x; 1.0475x over previous
#include <cuda_runtime.h>
#include <cstdint>

// Problem constants (fixed by the dataset)
#define NN      100000      // nodes
#define DIN     256         // input feature dim
#define DOUT    32          // output feature dim
#define GTHREADS 256        // 8 warps
#define RPW     16          // rows per warp (m16)
#define RPB     (RPW * 8)   // 128 rows per block
#define NKS     (DIN / 8)   // 32 k-steps of k8
#define CHUNK_COLS 32       // k-columns per pipeline chunk
#define KSPC    4           // k-steps per chunk
#define NCHUNK  (DIN / CHUNK_COLS)   // 8
#define XS_STRIDE 36        // floats per staged row (bank-spread, 16B aligned)
#define XBUF_FLOATS (RPB * XS_STRIDE)            // 4608 floats = 18 KB
#define BFRAG_N (NKS * 4 * 32)                   // 4096 uint2 total
#define BCHUNK_U2 (KSPC * 4 * 32)                // 512 uint2 = 4 KB per chunk
#define XBUF_BYTES (XBUF_FLOATS * 4)
#define BCHUNK_BYTES (BCHUNK_U2 * 8)
#define SMEM_BYTES (2 * (XBUF_BYTES + BCHUNK_BYTES))   // 44 KB

// ---- Device-global scratch (per rules) ----
__device__ float g_presup[(size_t)NN * DOUT];   // 12.8 MB
__device__ uint2 g_bfrag[BFRAG_N];              // 32 KB (fragment-ordered)

// ===========================================================================
// GEMM (tf32 mma.sync). B fragments precomputed once to global in fragment
// order; each block cp.asyncs the 4 KB B-slice of chunk c together with the
// X chunk (one commit group per chunk, double-buffered). Smem 44 KB ->
// 4 blocks/SM (occ ~50%) vs 3 before.
// ===========================================================================
__device__ __forceinline__ uint32_t f2tf32(float f) {
    uint32_t u;
    asm("cvt.rna.tf32.f32 %0, %1;" : "=r"(u) : "f"(f));
    return u;
}

__device__ __forceinline__ void mma_tf32(float4& d,
                                         uint32_t a0, uint32_t a1, uint32_t a2, uint32_t a3,
                                         uint32_t b0, uint32_t b1) {
    asm volatile("mma.sync.aligned.m16n8k8.row.col.f32.tf32.tf32.f32 "
                 "{%0,%1,%2,%3}, {%4,%5,%6,%7}, {%8,%9}, {%0,%1,%2,%3};"
                 : "+f"(d.x), "+f"(d.y), "+f"(d.z), "+f"(d.w)
                 : "r"(a0), "r"(a1), "r"(a2), "r"(a3), "r"(b0), "r"(b1));
}

__device__ __forceinline__ uint32_t smem_u32(const void* p) {
    uint32_t a;
    asm("{ .reg .u64 t; cvta.to.shared.u64 t, %1; cvt.u32.u64 %0, t; }"
        : "=r"(a) : "l"(p));
    return a;
}

__device__ __forceinline__ void cp_async16(uint32_t dst, const void* src, int nbytes) {
    asm volatile("cp.async.ca.shared.global [%0], [%1], 16, %2;"
                 :: "r"(dst), "l"(src), "r"(nbytes) : "memory");
}

// Issue cp.async for one chunk: X tile slice (32 cols x 128 rows) + B slice
// (4 KB of fragment-ordered g_bfrag). One commit group.
__device__ __forceinline__ void issue_chunk(uint32_t xs_addr, uint32_t bs_addr,
                                            const float* __restrict__ x,
                                            int row0, int cidx, int tid) {
    const int kc = cidx * CHUNK_COLS;
#pragma unroll
    for (int j = 0; j < 4; j++) {
        int i    = tid + j * GTHREADS;
        int r    = i >> 3;
        int seg  = i & 7;
        int grow = row0 + r;
        int gsrc = (grow < NN) ? grow : (NN - 1);
        const float* src = x + (size_t)gsrc * DIN + kc + seg * 4;
        uint32_t dst = xs_addr + (uint32_t)(r * (XS_STRIDE * 4) + seg * 16);
        cp_async16(dst, src, (grow < NN) ? 16 : 0);
    }
    // B slice: 4 KB = 256 x 16B; threads 0..255 one each
    {
        const char* bsrc = (const char*)(g_bfrag + (size_t)cidx * BCHUNK_U2) + tid * 16;
        cp_async16(bs_addr + tid * 16, bsrc, 16);
    }
    asm volatile("cp.async.commit_group;" ::: "memory");
}

// Precompute B fragments once (grid 16 x 256)
__global__ void bfrag_kernel(const float* __restrict__ w) {
    int i = blockIdx.x * 256 + threadIdx.x;
    if (i >= BFRAG_N) return;
    int ks  = i >> 7;
    int rem = i & 127;
    int nb  = rem >> 5;
    int ln  = rem & 31;
    int t = ln & 3, g = ln >> 2;
    float w0 = w[(ks * 8 + t)     * DOUT + nb * 8 + g];
    float w1 = w[(ks * 8 + t + 4) * DOUT + nb * 8 + g];
    g_bfrag[i] = make_uint2(f2tf32(w0), f2tf32(w1));
}

__global__ __launch_bounds__(GTHREADS, 4) void gemm_kernel(const float* __restrict__ x) {
    extern __shared__ char smem[];
    // Layout: Xbuf0 | Xbuf1 | Bbuf0 | Bbuf1
    float* Xbuf = (float*)smem;
    uint2* Bbuf = (uint2*)(smem + 2 * XBUF_BYTES);
    const uint32_t xb_addr0 = smem_u32(Xbuf);
    const uint32_t xb_addr1 = xb_addr0 + XBUF_BYTES;
    const uint32_t bb_addr0 = smem_u32(Bbuf);
    const uint32_t bb_addr1 = bb_addr0 + BCHUNK_BYTES;

    const int tid  = threadIdx.x;
    const int row0 = blockIdx.x * RPB;

    issue_chunk(xb_addr0, bb_addr0, x, row0, 0, tid);
    issue_chunk(xb_addr1, bb_addr1, x, row0, 1, tid);

    const int wid  = tid >> 5;
    const int lane = tid & 31;
    const int t    = lane & 3;
    const int g    = lane >> 2;
    const int rl   = wid * RPW;

    float4 acc[4];
#pragma unroll
    for (int nb = 0; nb < 4; nb++) acc[nb] = make_float4(0.f, 0.f, 0.f, 0.f);

    const int offA = (rl + g) * XS_STRIDE + t;
    const int offB = (rl + g + 8) * XS_STRIDE + t;

#pragma unroll
    for (int c = 0; c < NCHUNK; c++) {
        if (c < NCHUNK - 1)
            asm volatile("cp.async.wait_group 1;" ::: "memory");
        else
            asm volatile("cp.async.wait_group 0;" ::: "memory");
        __syncthreads();

        const float* Xs = Xbuf + (c & 1) * XBUF_FLOATS;
        const uint2* Bs = Bbuf + (c & 1) * BCHUNK_U2;
#pragma unroll
        for (int ksl = 0; ksl < KSPC; ksl++) {
            const int k0 = ksl * 8;
            uint32_t a0 = f2tf32(Xs[offA + k0]);
            uint32_t a1 = f2tf32(Xs[offB + k0]);
            uint32_t a2 = f2tf32(Xs[offA + k0 + 4]);
            uint32_t a3 = f2tf32(Xs[offB + k0 + 4]);

            const uint2* bp = Bs + ksl * 4 * 32 + lane;
            uint2 b0 = bp[0 * 32];
            uint2 b1 = bp[1 * 32];
            uint2 b2 = bp[2 * 32];
            uint2 b3 = bp[3 * 32];
            mma_tf32(acc[0], a0, a1, a2, a3, b0.x, b0.y);
            mma_tf32(acc[1], a0, a1, a2, a3, b1.x, b1.y);
            mma_tf32(acc[2], a0, a1, a2, a3, b2.x, b2.y);
            mma_tf32(acc[3], a0, a1, a2, a3, b3.x, b3.y);
        }

        if (c + 2 < NCHUNK) {
            __syncthreads();
            issue_chunk((c & 1) ? xb_addr1 : xb_addr0,
                        (c & 1) ? bb_addr1 : bb_addr0,
                        x, row0, c + 2, tid);
        }
    }

    const int r0 = row0 + rl + g;
    const int r1 = row0 + rl + g + 8;
#pragma unroll
    for (int nb = 0; nb < 4; nb++) {
        if (r0 < NN)
            *(float2*)(g_presup + (size_t)r0 * DOUT + nb * 8 + 2 * t) =
                make_float2(acc[nb].x, acc[nb].y);
        if (r1 < NN)
            *(float2*)(g_presup + (size_t)r1 * DOUT + nb * 8 + 2 * t) =
                make_float2(acc[nb].z, acc[nb].w);
    }
}

// ===========================================================================
// Scatter SpMM  out[row[e]] += val[e] * pre_sup[col[e]]
// Proven Round-8 version: 8 threads per edge (lane-level coalescing),
// one float4 gather + one red.global.add.v4.f32 per thread.
// ===========================================================================
__global__ __launch_bounds__(256) void scatter_kernel(const int*   __restrict__ arow,
                                                      const int*   __restrict__ acol,
                                                      const float* __restrict__ aval,
                                                      float*       __restrict__ out,
                                                      int n_edges) {
    long long gdx = (long long)blockIdx.x * blockDim.x + threadIdx.x;
    int e    = (int)(gdx >> 3);
    int part = (int)(gdx & 7);
    if (e >= n_edges) return;

    int   r = arow[e];
    int   c = acol[e];
    float v = aval[e];

    float4 p = *(const float4*)(g_presup + (size_t)c * DOUT + part * 4);
    float m0 = v * p.x, m1 = v * p.y, m2 = v * p.z, m3 = v * p.w;

    float* dst = out + (size_t)r * DOUT + part * 4;
    asm volatile("red.global.add.v4.f32 [%0], {%1, %2, %3, %4};"
                 :: "l"(dst), "f"(m0), "f"(m1), "f"(m2), "f"(m3)
                 : "memory");
}

// ===========================================================================
// ReLU in place: 4 float4 per thread (MLP=4) to approach DRAM floor.
// n4 = out_size/4 (float4 count), grid covers n4/4 threads.
// ===========================================================================
__global__ __launch_bounds__(256) void relu_kernel(float* __restrict__ out, int n4) {
    int base = (blockIdx.x * 256 + threadIdx.x) * 4;
    float4 v[4];
#pragma unroll
    for (int j = 0; j < 4; j++)
        if (base + j < n4) v[j] = ((float4*)out)[base + j];
#pragma unroll
    for (int j = 0; j < 4; j++) {
        if (base + j < n4) {
            v[j].x = fmaxf(v[j].x, 0.f);
            v[j].y = fmaxf(v[j].y, 0.f);
            v[j].z = fmaxf(v[j].z, 0.f);
            v[j].w = fmaxf(v[j].w, 0.f);
            ((float4*)out)[base + j] = v[j];
        }
    }
}

// ===========================================================================
// kernel_launch: bfrag -> memset(out) -> gemm -> scatter -> relu
// ===========================================================================
extern "C" void kernel_launch(void* const* d_in, const int* in_sizes, int n_in,
                              void* d_out, int out_size) {
    const float* x    = (const float*)d_in[0];
    const int*   arow = (const int*)  d_in[1];
    const int*   acol = (const int*)  d_in[2];
    const float* aval = (const float*)d_in[3];
    const float* w    = (const float*)d_in[4];
    float*       out  = (float*)d_out;

    const int n_edges = in_sizes[1];

    cudaFuncSetAttribute(gemm_kernel, cudaFuncAttributeMaxDynamicSharedMemorySize,
                         SMEM_BYTES);

    bfrag_kernel<<<(BFRAG_N + 255) / 256, 256>>>(w);
    cudaMemsetAsync(out, 0, (size_t)out_size * sizeof(float), 0);

    gemm_kernel<<<(NN + RPB - 1) / RPB, GTHREADS, SMEM_BYTES>>>(x);

    long long sthreads = (long long)n_edges * 8;
    int sblocks = (int)((sthreads + 255) / 256);
    scatter_kernel<<<sblocks, 256>>>(arow, acol, aval, out, n_edges);

    int n4 = out_size / 4;
    int rthreads = (n4 + 3) / 4;
    relu_kernel<<<(rthreads + 255) / 256, 256>>>(out, n4);
}

// round 14
// speedup vs baseline: 1.7550x; 1.0479x over previous
#include <cuda_runtime.h>
#include <cstdint>

// Problem constants (fixed by the dataset)
#define NN      100000      // nodes
#define DIN     256         // input feature dim
#define DOUT    32          // output feature dim
#define GTHREADS 256        // 8 warps
#define RPW     16          // rows per warp (m16)
#define RPB     (RPW * 8)   // 128 rows per block
#define NKS     (DIN / 8)   // 32 k-steps of k8
#define CHUNK_COLS 32       // k-columns per pipeline chunk
#define KSPC    4           // k-steps per chunk
#define NCHUNK  (DIN / CHUNK_COLS)   // 8
#define XS_STRIDE 36        // floats per staged row (bank-spread, 16B aligned)
#define XBUF_FLOATS (RPB * XS_STRIDE)            // 4608 floats = 18 KB
#define BFRAG_N (NKS * 4 * 32)                   // 4096 uint2 total
#define BCHUNK_U2 (KSPC * 4 * 32)                // 512 uint2 = 4 KB per chunk
#define XBUF_BYTES (XBUF_FLOATS * 4)
#define BCHUNK_BYTES (BCHUNK_U2 * 8)
#define SMEM_BYTES (2 * (XBUF_BYTES + BCHUNK_BYTES))   // 44 KB

// ---- Device-global scratch (per rules) ----
__device__ float g_presup[(size_t)NN * DOUT];   // 12.8 MB
__device__ uint2 g_bfrag[BFRAG_N];              // 32 KB (fragment-ordered)
// Atomic accumulation target. Zero-initialized at module load; the relu pass
// re-zeroes it every launch, so every kernel_launch sees it zeroed (determinism
// across graph replays).
__device__ float g_accum[(size_t)NN * DOUT];    // 12.8 MB

// ===========================================================================
// GEMM (tf32 mma.sync). B fragments precomputed once to global in fragment
// order; each block cp.asyncs the 4 KB B-slice of chunk c together with the
// X chunk (one commit group per chunk, double-buffered). Smem 44 KB.
// ===========================================================================
__device__ __forceinline__ uint32_t f2tf32(float f) {
    uint32_t u;
    asm("cvt.rna.tf32.f32 %0, %1;" : "=r"(u) : "f"(f));
    return u;
}

__device__ __forceinline__ void mma_tf32(float4& d,
                                         uint32_t a0, uint32_t a1, uint32_t a2, uint32_t a3,
                                         uint32_t b0, uint32_t b1) {
    asm volatile("mma.sync.aligned.m16n8k8.row.col.f32.tf32.tf32.f32 "
                 "{%0,%1,%2,%3}, {%4,%5,%6,%7}, {%8,%9}, {%0,%1,%2,%3};"
                 : "+f"(d.x), "+f"(d.y), "+f"(d.z), "+f"(d.w)
                 : "r"(a0), "r"(a1), "r"(a2), "r"(a3), "r"(b0), "r"(b1));
}

__device__ __forceinline__ uint32_t smem_u32(const void* p) {
    uint32_t a;
    asm("{ .reg .u64 t; cvta.to.shared.u64 t, %1; cvt.u32.u64 %0, t; }"
        : "=r"(a) : "l"(p));
    return a;
}

__device__ __forceinline__ void cp_async16(uint32_t dst, const void* src, int nbytes) {
    asm volatile("cp.async.ca.shared.global [%0], [%1], 16, %2;"
                 :: "r"(dst), "l"(src), "r"(nbytes) : "memory");
}

// Issue cp.async for one chunk: X tile slice (32 cols x 128 rows) + B slice
// (4 KB of fragment-ordered g_bfrag). One commit group.
__device__ __forceinline__ void issue_chunk(uint32_t xs_addr, uint32_t bs_addr,
                                            const float* __restrict__ x,
                                            int row0, int cidx, int tid) {
    const int kc = cidx * CHUNK_COLS;
#pragma unroll
    for (int j = 0; j < 4; j++) {
        int i    = tid + j * GTHREADS;
        int r    = i >> 3;
        int seg  = i & 7;
        int grow = row0 + r;
        int gsrc = (grow < NN) ? grow : (NN - 1);
        const float* src = x + (size_t)gsrc * DIN + kc + seg * 4;
        uint32_t dst = xs_addr + (uint32_t)(r * (XS_STRIDE * 4) + seg * 16);
        cp_async16(dst, src, (grow < NN) ? 16 : 0);
    }
    {
        const char* bsrc = (const char*)(g_bfrag + (size_t)cidx * BCHUNK_U2) + tid * 16;
        cp_async16(bs_addr + tid * 16, bsrc, 16);
    }
    asm volatile("cp.async.commit_group;" ::: "memory");
}

// Precompute B fragments once (grid 16 x 256)
__global__ void bfrag_kernel(const float* __restrict__ w) {
    int i = blockIdx.x * 256 + threadIdx.x;
    if (i >= BFRAG_N) return;
    int ks  = i >> 7;
    int rem = i & 127;
    int nb  = rem >> 5;
    int ln  = rem & 31;
    int t = ln & 3, g = ln >> 2;
    float w0 = w[(ks * 8 + t)     * DOUT + nb * 8 + g];
    float w1 = w[(ks * 8 + t + 4) * DOUT + nb * 8 + g];
    g_bfrag[i] = make_uint2(f2tf32(w0), f2tf32(w1));
}

__global__ __launch_bounds__(GTHREADS, 4) void gemm_kernel(const float* __restrict__ x) {
    extern __shared__ char smem[];
    float* Xbuf = (float*)smem;
    uint2* Bbuf = (uint2*)(smem + 2 * XBUF_BYTES);
    const uint32_t xb_addr0 = smem_u32(Xbuf);
    const uint32_t xb_addr1 = xb_addr0 + XBUF_BYTES;
    const uint32_t bb_addr0 = smem_u32(Bbuf);
    const uint32_t bb_addr1 = bb_addr0 + BCHUNK_BYTES;

    const int tid  = threadIdx.x;
    const int row0 = blockIdx.x * RPB;

    issue_chunk(xb_addr0, bb_addr0, x, row0, 0, tid);
    issue_chunk(xb_addr1, bb_addr1, x, row0, 1, tid);

    const int wid  = tid >> 5;
    const int lane = tid & 31;
    const int t    = lane & 3;
    const int g    = lane >> 2;
    const int rl   = wid * RPW;

    float4 acc[4];
#pragma unroll
    for (int nb = 0; nb < 4; nb++) acc[nb] = make_float4(0.f, 0.f, 0.f, 0.f);

    const int offA = (rl + g) * XS_STRIDE + t;
    const int offB = (rl + g + 8) * XS_STRIDE + t;

#pragma unroll
    for (int c = 0; c < NCHUNK; c++) {
        if (c < NCHUNK - 1)
            asm volatile("cp.async.wait_group 1;" ::: "memory");
        else
            asm volatile("cp.async.wait_group 0;" ::: "memory");
        __syncthreads();

        const float* Xs = Xbuf + (c & 1) * XBUF_FLOATS;
        const uint2* Bs = Bbuf + (c & 1) * BCHUNK_U2;
#pragma unroll
        for (int ksl = 0; ksl < KSPC; ksl++) {
            const int k0 = ksl * 8;
            uint32_t a0 = f2tf32(Xs[offA + k0]);
            uint32_t a1 = f2tf32(Xs[offB + k0]);
            uint32_t a2 = f2tf32(Xs[offA + k0 + 4]);
            uint32_t a3 = f2tf32(Xs[offB + k0 + 4]);

            const uint2* bp = Bs + ksl * 4 * 32 + lane;
            uint2 b0 = bp[0 * 32];
            uint2 b1 = bp[1 * 32];
            uint2 b2 = bp[2 * 32];
            uint2 b3 = bp[3 * 32];
            mma_tf32(acc[0], a0, a1, a2, a3, b0.x, b0.y);
            mma_tf32(acc[1], a0, a1, a2, a3, b1.x, b1.y);
            mma_tf32(acc[2], a0, a1, a2, a3, b2.x, b2.y);
            mma_tf32(acc[3], a0, a1, a2, a3, b3.x, b3.y);
        }

        if (c + 2 < NCHUNK) {
            __syncthreads();
            issue_chunk((c & 1) ? xb_addr1 : xb_addr0,
                        (c & 1) ? bb_addr1 : bb_addr0,
                        x, row0, c + 2, tid);
        }
    }

    // Epilogue: one float4 store per (row, nb-pair)
    const int r0 = row0 + rl + g;
    const int r1 = row0 + rl + g + 8;
#pragma unroll
    for (int h = 0; h < 2; h++) {
        // pair (nb = 2h, 2h+1): row-g values (x,y of each) and row-g+8 (z,w)
        float4 lo = make_float4(acc[2*h].x, acc[2*h].y, acc[2*h+1].x, acc[2*h+1].y);
        float4 hi = make_float4(acc[2*h].z, acc[2*h].w, acc[2*h+1].z, acc[2*h+1].w);
        // columns: nb*8 + 2t .. but pair spans cols [16h + 2t, 16h + 2t + 1] and
        // [16h + 8 + 2t, ...] -> NOT contiguous across nb. Store per-nb float2 instead.
        (void)lo; (void)hi;
    }
    // (contiguity check failed above -> keep proven float2 stores)
#pragma unroll
    for (int nb = 0; nb < 4; nb++) {
        if (r0 < NN)
            *(float2*)(g_presup + (size_t)r0 * DOUT + nb * 8 + 2 * t) =
                make_float2(acc[nb].x, acc[nb].y);
        if (r1 < NN)
            *(float2*)(g_presup + (size_t)r1 * DOUT + nb * 8 + 2 * t) =
                make_float2(acc[nb].z, acc[nb].w);
    }
}

// ===========================================================================
// Scatter SpMM  g_accum[row[e]] += val[e] * pre_sup[col[e]]
// Proven Round-8 shape: 8 threads per edge (lane-level coalescing),
// one float4 gather + one red.global.add.v4.f32 per thread.
// g_accum is guaranteed zero on entry (module init + relu re-zeroes).
// ===========================================================================
__global__ __launch_bounds__(256) void scatter_kernel(const int*   __restrict__ arow,
                                                      const int*   __restrict__ acol,
                                                      const float* __restrict__ aval,
                                                      int n_edges) {
    long long gdx = (long long)blockIdx.x * blockDim.x + threadIdx.x;
    int e    = (int)(gdx >> 3);
    int part = (int)(gdx & 7);
    if (e >= n_edges) return;

    int   r = arow[e];
    int   c = acol[e];
    float v = aval[e];

    float4 p = *(const float4*)(g_presup + (size_t)c * DOUT + part * 4);
    float m0 = v * p.x, m1 = v * p.y, m2 = v * p.z, m3 = v * p.w;

    float* dst = g_accum + (size_t)r * DOUT + part * 4;
    asm volatile("red.global.add.v4.f32 [%0], {%1, %2, %3, %4};"
                 :: "l"(dst), "f"(m0), "f"(m1), "f"(m2), "f"(m3)
                 : "memory");
}

// ===========================================================================
// ReLU: out = relu(g_accum); g_accum = 0 (restores invariant for next launch)
// ===========================================================================
__global__ __launch_bounds__(256) void relu_kernel(float* __restrict__ out, int n4) {
    int i = blockIdx.x * 256 + threadIdx.x;
    if (i < n4) {
        float4 v = ((const float4*)g_accum)[i];
        v.x = fmaxf(v.x, 0.f);
        v.y = fmaxf(v.y, 0.f);
        v.z = fmaxf(v.z, 0.f);
        v.w = fmaxf(v.w, 0.f);
        ((float4*)out)[i] = v;
        ((float4*)g_accum)[i] = make_float4(0.f, 0.f, 0.f, 0.f);
    }
}

// ===========================================================================
// kernel_launch: bfrag -> gemm -> scatter -> relu (no memset needed)
// ===========================================================================
extern "C" void kernel_launch(void* const* d_in, const int* in_sizes, int n_in,
                              void* d_out, int out_size) {
    const float* x    = (const float*)d_in[0];
    const int*   arow = (const int*)  d_in[1];
    const int*   acol = (const int*)  d_in[2];
    const float* aval = (const float*)d_in[3];
    const float* w    = (const float*)d_in[4];
    float*       out  = (float*)d_out;

    const int n_edges = in_sizes[1];

    cudaFuncSetAttribute(gemm_kernel, cudaFuncAttributeMaxDynamicSharedMemorySize,
                         SMEM_BYTES);

    bfrag_kernel<<<(BFRAG_N + 255) / 256, 256>>>(w);

    gemm_kernel<<<(NN + RPB - 1) / RPB, GTHREADS, SMEM_BYTES>>>(x);

    long long sthreads = (long long)n_edges * 8;
    int sblocks = (int)((sthreads + 255) / 256);
    scatter_kernel<<<sblocks, 256>>>(arow, acol, aval, n_edges);

    int n4 = out_size / 4;
    relu_kernel<<<(n4 + 255) / 256, 256>>>(out, n4);
}